// round 3
// baseline (speedup 1.0000x reference)
#include <cuda_runtime.h>
#include <math.h>

// ---------------- problem constants ----------------
#define N1C 50000
#define E1C 1000000
#define N2C 199
#define E2C 4000
#define FIN 128
#define BATCH 10
#define NPG 5000
#define TOPK 50
#define LN_EPS 1e-5f

static inline int cdiv(int a, int b) { return (a + b - 1) / b; }

// ---------------- scratch (device globals; no allocation allowed) ----------------
__device__ float d_z1[N1C * 128];     // pre-aggregation transform (layer1: 128-wide; layer2 reuse: 64-wide)
__device__ float d_mean1[N1C * 128];  // aggregated mean (layer1 128-wide; layer2 reuse 64-wide)
__device__ float d_h1[N1C * 128];     // layer1 output
__device__ float d_o1[N1C * 64];      // layer2 output (out1)
__device__ int d_cnt1[N1C];
__device__ int d_offs1[N1C + 1];
__device__ int d_cur1[N1C];
__device__ int d_csr1[E1C];

__device__ float d_z2[N2C * 128];
__device__ float d_mean2[N2C * 128];
__device__ float d_h2[N2C * 128];
__device__ float d_o2[N2C * 64];
__device__ int d_cnt2[N2C];
__device__ int d_offs2[N2C + 1];
__device__ int d_cur2[N2C];
__device__ int d_csr2[E2C];

__device__ unsigned long long d_codes[N1C];
__device__ int d_sel[BATCH * TOPK];
__device__ float d_feat[BATCH * TOPK * N2C];
__device__ float d_pre1[BATCH * 128];

// ---------------- small utility kernels ----------------
__global__ void zero_int_kernel(int* p, int n) {
    int i = blockIdx.x * blockDim.x + threadIdx.x;
    if (i < n) p[i] = 0;
}

// edge_index layout: [2, E] row-major -> src = ei[e], dst = ei[E + e]
__global__ void count_kernel(const int* __restrict__ ei, int E, int* __restrict__ cnt) {
    int e = blockIdx.x * blockDim.x + threadIdx.x;
    if (e < E) atomicAdd(&cnt[ei[E + e]], 1);
}

// single-block exclusive scan (n <= ~64k): offs[i] = sum_{j<i} cnt[j]; cur = copy; offs[n] = total
__global__ void scan_kernel(const int* __restrict__ cnt, int* __restrict__ offs,
                            int* __restrict__ cur, int n) {
    __shared__ int sh[1024];
    __shared__ int carry_s;
    int t = threadIdx.x;
    if (t == 0) carry_s = 0;
    __syncthreads();
    for (int base = 0; base < n; base += 1024) {
        int v = (base + t < n) ? cnt[base + t] : 0;
        sh[t] = v;
        __syncthreads();
        for (int off = 1; off < 1024; off <<= 1) {
            int a = (t >= off) ? sh[t - off] : 0;
            __syncthreads();
            sh[t] += a;
            __syncthreads();
        }
        int c = carry_s;
        int excl = c + sh[t] - v;
        if (base + t < n) { offs[base + t] = excl; cur[base + t] = excl; }
        int tot = sh[1023];
        __syncthreads();
        if (t == 0) carry_s = c + tot;
        __syncthreads();
    }
    if (t == 0) offs[n] = carry_s;
}

__global__ void fill_kernel(const int* __restrict__ ei, int E,
                            int* __restrict__ cur, int* __restrict__ csr) {
    int e = blockIdx.x * blockDim.x + threadIdx.x;
    if (e < E) {
        int dst = ei[E + e];
        int pos = atomicAdd(&cur[dst], 1);
        csr[pos] = ei[e];  // src
    }
}

// ---------------- fp32 GEMM, K=128 fixed: out[M,BN] = A[M,128] @ W[BN,128]^T (+epi) ----------------
template <int BN, bool EPI>
__global__ void gemm_k128(const float* __restrict__ A, const float* __restrict__ W,
                          const float* __restrict__ bias, const float* __restrict__ addm,
                          float* __restrict__ out, int M) {
    const int BM = 128, BK = 32;
    const int TM = 8, TN = BN / 16;
    __shared__ float As[BM][BK + 1];
    __shared__ float Ws[BK][BN + 4];
    int t = threadIdx.x;  // 256
    int tx = t & 15, ty = t >> 4;
    int row0 = blockIdx.x * BM;
    float acc[TM][TN];
#pragma unroll
    for (int i = 0; i < TM; i++)
#pragma unroll
        for (int j = 0; j < TN; j++) acc[i][j] = 0.f;

    for (int k0 = 0; k0 < 128; k0 += BK) {
        // A tile: BM x BK
#pragma unroll
        for (int i = 0; i < (BM * BK) / 256; i++) {
            int idx = t + i * 256;
            int r = idx >> 5, k = idx & 31;
            int gr = row0 + r;
            As[r][k] = (gr < M) ? A[gr * 128 + k0 + k] : 0.f;
        }
        // W tile: BN x BK, stored transposed Ws[k][n]
#pragma unroll
        for (int i = 0; i < (BN * BK) / 256; i++) {
            int idx = t + i * 256;
            int n = idx >> 5, k = idx & 31;
            Ws[k][n] = W[n * 128 + k0 + k];
        }
        __syncthreads();
#pragma unroll 8
        for (int k = 0; k < BK; k++) {
            float af[TM], bf[TN];
#pragma unroll
            for (int i = 0; i < TM; i++) af[i] = As[ty * TM + i][k];
#pragma unroll
            for (int j = 0; j < TN; j++) bf[j] = Ws[k][tx * TN + j];
#pragma unroll
            for (int i = 0; i < TM; i++)
#pragma unroll
                for (int j = 0; j < TN; j++) acc[i][j] += af[i] * bf[j];
        }
        __syncthreads();
    }
#pragma unroll
    for (int i = 0; i < TM; i++) {
        int r = row0 + ty * TM + i;
        if (r < M) {
#pragma unroll
            for (int j = 0; j < TN; j++) {
                int c = tx * TN + j;
                float v = acc[i][j];
                if (EPI) v = fmaxf(v + addm[r * BN + c] + bias[c], 0.f);
                out[r * BN + c] = v;
            }
        }
    }
}

// ---------------- CSR gather mean aggregation: mean[node] = sum(z[src]) / max(deg,1) ----------------
template <int F>
__global__ void agg_kernel(const float* __restrict__ z, const int* __restrict__ offs,
                           const int* __restrict__ csr, float* __restrict__ mean) {
    int node = blockIdx.x;
    int f = threadIdx.x;  // F threads
    int s = offs[node], e = offs[node + 1];
    float acc = 0.f;
    for (int i = s; i < e; i++) {
        int src = csr[i];
        acc += z[src * F + f];
    }
    float inv = 1.f / fmaxf((float)(e - s), 1.f);
    mean[node * F + f] = acc * inv;
}

// ---------------- sort key per node: d2 to out2's last row; pack for stable descending top-k ----------------
__global__ void key_kernel(const float* __restrict__ o1, const float* __restrict__ o2last,
                           unsigned long long* __restrict__ codes, int n) {
    int i = blockIdx.x * blockDim.x + threadIdx.x;
    if (i >= n) return;
    const float* r = o1 + (long)i * 64;
    float a2 = 0.f, dot = 0.f, b2 = 0.f;
#pragma unroll 8
    for (int d = 0; d < 64; d++) {
        float v = r[d], w = o2last[d];
        a2 += v * v;
        dot += v * w;
        b2 += w * w;
    }
    float key = a2 + b2 - 2.f * dot;  // ordering by d2 == ordering by dist
    unsigned u = __float_as_uint(key);
    u = (u & 0x80000000u) ? ~u : (u | 0x80000000u);  // monotone float->uint
    // ascending code order == descending key, ties broken by smaller index (matches stable argsort(-key))
    codes[i] = ((unsigned long long)(~u) << 32) | (unsigned)i;
}

__device__ __forceinline__ unsigned long long umin64(unsigned long long a, unsigned long long b) {
    return a < b ? a : b;
}

// one block per graph: select 50 smallest codes, in order
__global__ void topk_kernel(unsigned long long* __restrict__ codes, int* __restrict__ sel) {
    __shared__ unsigned long long s[NPG];
    __shared__ unsigned long long red[512];
    int b = blockIdx.x;
    int t = threadIdx.x;  // 512
    for (int i = t; i < NPG; i += 512) s[i] = codes[b * NPG + i];
    __syncthreads();
    for (int k = 0; k < TOPK; k++) {
        unsigned long long m = ~0ull;
        for (int i = t; i < NPG; i += 512) m = umin64(m, s[i]);
        red[t] = m;
        __syncthreads();
        for (int off = 256; off; off >>= 1) {
            if (t < off) red[t] = umin64(red[t], red[t + off]);
            __syncthreads();
        }
        unsigned long long best = red[0];
        int gidx = (int)(best & 0xffffffffu);
        if (t == 0) sel[b * TOPK + k] = gidx;
        __syncthreads();
        if (t == 0) s[gidx - b * NPG] = ~0ull;
        __syncthreads();
    }
}

// dist rows for selected nodes only: feat[bk, j] = sqrt(max(a2 + b2_j - 2*dot, 0))
__global__ void dist_kernel(const float* __restrict__ o1, const float* __restrict__ o2,
                            const int* __restrict__ sel, float* __restrict__ feat, int n2) {
    __shared__ float o1s[64];
    int bk = blockIdx.x;
    int t = threadIdx.x;  // 256
    int g = sel[bk];
    if (t < 64) o1s[t] = o1[(long)g * 64 + t];
    __syncthreads();
    if (t < n2) {
        float a2 = 0.f, b2 = 0.f, dot = 0.f;
        const float* q = o2 + (long)t * 64;
#pragma unroll 8
        for (int d = 0; d < 64; d++) {
            float v = o1s[d], w = q[d];
            a2 += v * v;
            b2 += w * w;
            dot += v * w;
        }
        float d2 = a2 + b2 - 2.f * dot;
        feat[bk * n2 + t] = sqrtf(fmaxf(d2, 0.f));
    }
}

// fc1: pre1[b, o] = feat[b,:] . fc1_w[o,:] + fc1_b[o]
__global__ void fc1_kernel(const float* __restrict__ feat, const float* __restrict__ w,
                           const float* __restrict__ bias, float* __restrict__ pre, int L) {
    __shared__ float red[256];
    int o = blockIdx.x, b = blockIdx.y, t = threadIdx.x;
    const float* f = feat + (long)b * L;
    const float* wr = w + (long)o * L;
    float acc = 0.f;
    for (int i = t; i < L; i += 256) acc += f[i] * wr[i];
    red[t] = acc;
    __syncthreads();
    for (int off = 128; off; off >>= 1) {
        if (t < off) red[t] += red[t + off];
        __syncthreads();
    }
    if (t == 0) pre[b * 128 + o] = red[0] + bias[o];
}

__device__ __forceinline__ float bsum128(float v, float* red) {
    int t = threadIdx.x;
    red[t] = v;
    __syncthreads();
#pragma unroll
    for (int off = 64; off; off >>= 1) {
        if (t < off) red[t] += red[t + off];
        __syncthreads();
    }
    float s = red[0];
    __syncthreads();
    return s;
}

// LN1 + relu + fc2 + LN2 + relu + fc3 + sigmoid, one block per batch row (128 threads)
__global__ void head_kernel(const float* __restrict__ pre, const float* __restrict__ g1,
                            const float* __restrict__ bb1, const float* __restrict__ w2,
                            const float* __restrict__ b2v, const float* __restrict__ g2,
                            const float* __restrict__ bb2, const float* __restrict__ w3,
                            const float* __restrict__ b3, float* __restrict__ out) {
    __shared__ float red[128];
    __shared__ float ybuf[128];
    int b = blockIdx.x, t = threadIdx.x;
    float x = pre[b * 128 + t];
    float mu = bsum128(x, red) * (1.f / 128.f);
    float d = x - mu;
    float var = bsum128(d * d, red) * (1.f / 128.f);
    float y = fmaxf(d * rsqrtf(var + LN_EPS) * g1[t] + bb1[t], 0.f);
    ybuf[t] = y;
    __syncthreads();
    float p = 0.f;
    if (t < 64) {
        const float* wr = w2 + t * 128;
#pragma unroll 8
        for (int i = 0; i < 128; i++) p += ybuf[i] * wr[i];
        p += b2v[t];
    }
    float mu2 = bsum128((t < 64) ? p : 0.f, red) * (1.f / 64.f);
    float dd = p - mu2;
    float var2 = bsum128((t < 64) ? dd * dd : 0.f, red) * (1.f / 64.f);
    float z = (t < 64) ? fmaxf(dd * rsqrtf(var2 + LN_EPS) * g2[t] + bb2[t], 0.f) : 0.f;
    float s = bsum128((t < 64) ? z * w3[t] : 0.f, red);
    if (t == 0) out[b] = 1.f / (1.f + expf(-(s + b3[0])));
}

// ---------------- launch ----------------
extern "C" void kernel_launch(void* const* d_in, const int* in_sizes, int n_in,
                              void* d_out, int out_size) {
    const float* x1 = (const float*)d_in[0];
    const int* ei1 = (const int*)d_in[1];
    const float* x2 = (const float*)d_in[3];
    const int* ei2 = (const int*)d_in[4];
    const float* w1l = (const float*)d_in[5];
    const float* b1l = (const float*)d_in[6];
    const float* w1r = (const float*)d_in[7];
    const float* w2l = (const float*)d_in[8];
    const float* b2l = (const float*)d_in[9];
    const float* w2r = (const float*)d_in[10];
    const float* fc1w = (const float*)d_in[11];
    const float* fc1b = (const float*)d_in[12];
    const float* ln1g = (const float*)d_in[13];
    const float* ln1b = (const float*)d_in[14];
    const float* fc2w = (const float*)d_in[15];
    const float* fc2b = (const float*)d_in[16];
    const float* ln2g = (const float*)d_in[17];
    const float* ln2b = (const float*)d_in[18];
    const float* fc3w = (const float*)d_in[19];
    const float* fc3b = (const float*)d_in[20];
    float* out = (float*)d_out;

    int N1 = in_sizes[0] / FIN;
    int E1 = in_sizes[1] / 2;
    int N2 = in_sizes[3] / FIN;
    int E2 = in_sizes[4] / 2;

    void* p;
    float *z1, *mean1, *h1, *o1, *z2, *mean2, *h2, *o2, *feat, *pre1;
    int *cnt1, *offs1, *cur1, *csr1, *cnt2, *offs2, *cur2, *csr2, *sel;
    unsigned long long* codes;
    cudaGetSymbolAddress(&p, d_z1);    z1 = (float*)p;
    cudaGetSymbolAddress(&p, d_mean1); mean1 = (float*)p;
    cudaGetSymbolAddress(&p, d_h1);    h1 = (float*)p;
    cudaGetSymbolAddress(&p, d_o1);    o1 = (float*)p;
    cudaGetSymbolAddress(&p, d_cnt1);  cnt1 = (int*)p;
    cudaGetSymbolAddress(&p, d_offs1); offs1 = (int*)p;
    cudaGetSymbolAddress(&p, d_cur1);  cur1 = (int*)p;
    cudaGetSymbolAddress(&p, d_csr1);  csr1 = (int*)p;
    cudaGetSymbolAddress(&p, d_z2);    z2 = (float*)p;
    cudaGetSymbolAddress(&p, d_mean2); mean2 = (float*)p;
    cudaGetSymbolAddress(&p, d_h2);    h2 = (float*)p;
    cudaGetSymbolAddress(&p, d_o2);    o2 = (float*)p;
    cudaGetSymbolAddress(&p, d_cnt2);  cnt2 = (int*)p;
    cudaGetSymbolAddress(&p, d_offs2); offs2 = (int*)p;
    cudaGetSymbolAddress(&p, d_cur2);  cur2 = (int*)p;
    cudaGetSymbolAddress(&p, d_csr2);  csr2 = (int*)p;
    cudaGetSymbolAddress(&p, d_codes); codes = (unsigned long long*)p;
    cudaGetSymbolAddress(&p, d_sel);   sel = (int*)p;
    cudaGetSymbolAddress(&p, d_feat);  feat = (float*)p;
    cudaGetSymbolAddress(&p, d_pre1);  pre1 = (float*)p;

    // ---- CSR build (both graphs) ----
    zero_int_kernel<<<cdiv(N1, 256), 256>>>(cnt1, N1);
    zero_int_kernel<<<1, 256>>>(cnt2, N2);
    count_kernel<<<cdiv(E1, 256), 256>>>(ei1, E1, cnt1);
    count_kernel<<<cdiv(E2, 256), 256>>>(ei2, E2, cnt2);
    scan_kernel<<<1, 1024>>>(cnt1, offs1, cur1, N1);
    scan_kernel<<<1, 1024>>>(cnt2, offs2, cur2, N2);
    fill_kernel<<<cdiv(E1, 256), 256>>>(ei1, E1, cur1, csr1);
    fill_kernel<<<cdiv(E2, 256), 256>>>(ei2, E2, cur2, csr2);

    // ---- graph1 GNN ----
    gemm_k128<128, false><<<cdiv(N1, 128), 256>>>(x1, w1l, nullptr, nullptr, z1, N1);
    agg_kernel<128><<<N1, 128>>>(z1, offs1, csr1, mean1);
    gemm_k128<128, true><<<cdiv(N1, 128), 256>>>(x1, w1r, b1l, mean1, h1, N1);
    gemm_k128<64, false><<<cdiv(N1, 128), 256>>>(h1, w2l, nullptr, nullptr, z1, N1);
    agg_kernel<64><<<N1, 64>>>(z1, offs1, csr1, mean1);
    gemm_k128<64, true><<<cdiv(N1, 128), 256>>>(h1, w2r, b2l, mean1, o1, N1);

    // ---- graph2 GNN (tiny) ----
    gemm_k128<128, false><<<cdiv(N2, 128), 256>>>(x2, w1l, nullptr, nullptr, z2, N2);
    agg_kernel<128><<<N2, 128>>>(z2, offs2, csr2, mean2);
    gemm_k128<128, true><<<cdiv(N2, 128), 256>>>(x2, w1r, b1l, mean2, h2, N2);
    gemm_k128<64, false><<<cdiv(N2, 128), 256>>>(h2, w2l, nullptr, nullptr, z2, N2);
    agg_kernel<64><<<N2, 64>>>(z2, offs2, csr2, mean2);
    gemm_k128<64, true><<<cdiv(N2, 128), 256>>>(h2, w2r, b2l, mean2, o2, N2);

    // ---- key + top-k + sparse dist + MLP head ----
    key_kernel<<<cdiv(N1, 256), 256>>>(o1, o2 + (long)(N2 - 1) * 64, codes, N1);
    topk_kernel<<<BATCH, 512>>>(codes, sel);
    dist_kernel<<<BATCH * TOPK, 256>>>(o1, o2, sel, feat, N2);
    fc1_kernel<<<dim3(128, BATCH), 256>>>(feat, fc1w, fc1b, pre1, TOPK * N2);
    head_kernel<<<BATCH, 128>>>(pre1, ln1g, ln1b, fc2w, fc2b, ln2g, ln2b, fc3w, fc3b, out);
}

// round 4
// speedup vs baseline: 1.0038x; 1.0038x over previous
#include <cuda_runtime.h>
#include <math.h>

// ---------------- problem constants ----------------
#define N1C 50000
#define E1C 1000000
#define N2C 199
#define E2C 4000
#define FIN 128
#define BATCH 10
#define NPG 5000
#define TOPK 50
#define LN_EPS 1e-5f

static inline int cdiv(int a, int b) { return (a + b - 1) / b; }

// ---------------- scratch (device globals; no allocation allowed) ----------------
__device__ float d_z1[N1C * 128];     // pre-aggregation transform (layer1: 128-wide; layer2 reuse: 64-wide)
__device__ float d_mean1[N1C * 128];  // aggregated mean (layer1 128-wide; layer2 reuse 64-wide)
__device__ float d_h1[N1C * 128];     // layer1 output
__device__ float d_o1[N1C * 64];      // layer2 output (out1)
__device__ int d_cnt1[N1C];
__device__ int d_offs1[N1C + 1];
__device__ int d_cur1[N1C];
__device__ int d_csr1[E1C];

__device__ float d_z2[N2C * 128];
__device__ float d_mean2[N2C * 128];
__device__ float d_h2[N2C * 128];
__device__ float d_o2[N2C * 64];
__device__ int d_cnt2[N2C];
__device__ int d_offs2[N2C + 1];
__device__ int d_cur2[N2C];
__device__ int d_csr2[E2C];

__device__ unsigned long long d_codes[N1C];
__device__ int d_sel[BATCH * TOPK];
__device__ float d_feat[BATCH * TOPK * N2C];
__device__ float d_pre1[BATCH * 128];

// ---------------- small utility kernels ----------------
__global__ void zero_int_kernel(int* p, int n) {
    int i = blockIdx.x * blockDim.x + threadIdx.x;
    if (i < n) p[i] = 0;
}

// edge_index layout: [2, E] row-major -> src = ei[e], dst = ei[E + e]
__global__ void count_kernel(const int* __restrict__ ei, int E, int* __restrict__ cnt) {
    int e = blockIdx.x * blockDim.x + threadIdx.x;
    if (e < E) atomicAdd(&cnt[ei[E + e]], 1);
}

// single-block exclusive scan (n <= ~64k): offs[i] = sum_{j<i} cnt[j]; cur = copy; offs[n] = total
__global__ void scan_kernel(const int* __restrict__ cnt, int* __restrict__ offs,
                            int* __restrict__ cur, int n) {
    __shared__ int sh[1024];
    __shared__ int carry_s;
    int t = threadIdx.x;
    if (t == 0) carry_s = 0;
    __syncthreads();
    for (int base = 0; base < n; base += 1024) {
        int v = (base + t < n) ? cnt[base + t] : 0;
        sh[t] = v;
        __syncthreads();
        for (int off = 1; off < 1024; off <<= 1) {
            int a = (t >= off) ? sh[t - off] : 0;
            __syncthreads();
            sh[t] += a;
            __syncthreads();
        }
        int c = carry_s;
        int excl = c + sh[t] - v;
        if (base + t < n) { offs[base + t] = excl; cur[base + t] = excl; }
        int tot = sh[1023];
        __syncthreads();
        if (t == 0) carry_s = c + tot;
        __syncthreads();
    }
    if (t == 0) offs[n] = carry_s;
}

__global__ void fill_kernel(const int* __restrict__ ei, int E,
                            int* __restrict__ cur, int* __restrict__ csr) {
    int e = blockIdx.x * blockDim.x + threadIdx.x;
    if (e < E) {
        int dst = ei[E + e];
        int pos = atomicAdd(&cur[dst], 1);
        csr[pos] = ei[e];  // src
    }
}

// ---------------- fp32 GEMM, K=128 fixed: out[M,BN] = A[M,128] @ W[BN,128]^T (+epi) ----------------
template <int BN, bool EPI>
__global__ void gemm_k128(const float* __restrict__ A, const float* __restrict__ W,
                          const float* __restrict__ bias, const float* __restrict__ addm,
                          float* __restrict__ out, int M) {
    const int BM = 128, BK = 32;
    const int TM = 8, TN = BN / 16;
    __shared__ float As[BM][BK + 1];
    __shared__ float Ws[BK][BN + 4];
    int t = threadIdx.x;  // 256
    int tx = t & 15, ty = t >> 4;
    int row0 = blockIdx.x * BM;
    float acc[TM][TN];
#pragma unroll
    for (int i = 0; i < TM; i++)
#pragma unroll
        for (int j = 0; j < TN; j++) acc[i][j] = 0.f;

    for (int k0 = 0; k0 < 128; k0 += BK) {
        // A tile: BM x BK
#pragma unroll
        for (int i = 0; i < (BM * BK) / 256; i++) {
            int idx = t + i * 256;
            int r = idx >> 5, k = idx & 31;
            int gr = row0 + r;
            As[r][k] = (gr < M) ? A[gr * 128 + k0 + k] : 0.f;
        }
        // W tile: BN x BK, stored transposed Ws[k][n]
#pragma unroll
        for (int i = 0; i < (BN * BK) / 256; i++) {
            int idx = t + i * 256;
            int n = idx >> 5, k = idx & 31;
            Ws[k][n] = W[n * 128 + k0 + k];
        }
        __syncthreads();
#pragma unroll 8
        for (int k = 0; k < BK; k++) {
            float af[TM], bf[TN];
#pragma unroll
            for (int i = 0; i < TM; i++) af[i] = As[ty * TM + i][k];
#pragma unroll
            for (int j = 0; j < TN; j++) bf[j] = Ws[k][tx * TN + j];
#pragma unroll
            for (int i = 0; i < TM; i++)
#pragma unroll
                for (int j = 0; j < TN; j++) acc[i][j] += af[i] * bf[j];
        }
        __syncthreads();
    }
#pragma unroll
    for (int i = 0; i < TM; i++) {
        int r = row0 + ty * TM + i;
        if (r < M) {
#pragma unroll
            for (int j = 0; j < TN; j++) {
                int c = tx * TN + j;
                float v = acc[i][j];
                if (EPI) v = fmaxf(v + addm[r * BN + c] + bias[c], 0.f);
                out[r * BN + c] = v;
            }
        }
    }
}

// ---------------- CSR gather mean aggregation: mean[node] = sum(z[src]) / max(deg,1) ----------------
template <int F>
__global__ void agg_kernel(const float* __restrict__ z, const int* __restrict__ offs,
                           const int* __restrict__ csr, float* __restrict__ mean) {
    int node = blockIdx.x;
    int f = threadIdx.x;  // F threads
    int s = offs[node], e = offs[node + 1];
    float acc = 0.f;
    for (int i = s; i < e; i++) {
        int src = csr[i];
        acc += z[src * F + f];
    }
    float inv = 1.f / fmaxf((float)(e - s), 1.f);
    mean[node * F + f] = acc * inv;
}

// ---------------- sort key per node: d2 to out2's last row; pack for stable descending top-k ----------------
__global__ void key_kernel(const float* __restrict__ o1, const float* __restrict__ o2last,
                           unsigned long long* __restrict__ codes, int n) {
    int i = blockIdx.x * blockDim.x + threadIdx.x;
    if (i >= n) return;
    const float* r = o1 + (long)i * 64;
    float a2 = 0.f, dot = 0.f, b2 = 0.f;
#pragma unroll 8
    for (int d = 0; d < 64; d++) {
        float v = r[d], w = o2last[d];
        a2 += v * v;
        dot += v * w;
        b2 += w * w;
    }
    float key = a2 + b2 - 2.f * dot;  // ordering by d2 == ordering by dist
    unsigned u = __float_as_uint(key);
    u = (u & 0x80000000u) ? ~u : (u | 0x80000000u);  // monotone float->uint
    // ascending code order == descending key, ties broken by smaller index (matches stable argsort(-key))
    codes[i] = ((unsigned long long)(~u) << 32) | (unsigned)i;
}

__device__ __forceinline__ unsigned long long umin64(unsigned long long a, unsigned long long b) {
    return a < b ? a : b;
}

// one block per graph: select 50 smallest codes, in order
__global__ void topk_kernel(unsigned long long* __restrict__ codes, int* __restrict__ sel) {
    __shared__ unsigned long long s[NPG];
    __shared__ unsigned long long red[512];
    int b = blockIdx.x;
    int t = threadIdx.x;  // 512
    for (int i = t; i < NPG; i += 512) s[i] = codes[b * NPG + i];
    __syncthreads();
    for (int k = 0; k < TOPK; k++) {
        unsigned long long m = ~0ull;
        for (int i = t; i < NPG; i += 512) m = umin64(m, s[i]);
        red[t] = m;
        __syncthreads();
        for (int off = 256; off; off >>= 1) {
            if (t < off) red[t] = umin64(red[t], red[t + off]);
            __syncthreads();
        }
        unsigned long long best = red[0];
        int gidx = (int)(best & 0xffffffffu);
        if (t == 0) sel[b * TOPK + k] = gidx;
        __syncthreads();
        if (t == 0) s[gidx - b * NPG] = ~0ull;
        __syncthreads();
    }
}

// dist rows for selected nodes only: feat[bk, j] = sqrt(max(a2 + b2_j - 2*dot, 0))
__global__ void dist_kernel(const float* __restrict__ o1, const float* __restrict__ o2,
                            const int* __restrict__ sel, float* __restrict__ feat, int n2) {
    __shared__ float o1s[64];
    int bk = blockIdx.x;
    int t = threadIdx.x;  // 256
    int g = sel[bk];
    if (t < 64) o1s[t] = o1[(long)g * 64 + t];
    __syncthreads();
    if (t < n2) {
        float a2 = 0.f, b2 = 0.f, dot = 0.f;
        const float* q = o2 + (long)t * 64;
#pragma unroll 8
        for (int d = 0; d < 64; d++) {
            float v = o1s[d], w = q[d];
            a2 += v * v;
            b2 += w * w;
            dot += v * w;
        }
        float d2 = a2 + b2 - 2.f * dot;
        feat[bk * n2 + t] = sqrtf(fmaxf(d2, 0.f));
    }
}

// fc1: pre1[b, o] = feat[b,:] . fc1_w[o,:] + fc1_b[o]
__global__ void fc1_kernel(const float* __restrict__ feat, const float* __restrict__ w,
                           const float* __restrict__ bias, float* __restrict__ pre, int L) {
    __shared__ float red[256];
    int o = blockIdx.x, b = blockIdx.y, t = threadIdx.x;
    const float* f = feat + (long)b * L;
    const float* wr = w + (long)o * L;
    float acc = 0.f;
    for (int i = t; i < L; i += 256) acc += f[i] * wr[i];
    red[t] = acc;
    __syncthreads();
    for (int off = 128; off; off >>= 1) {
        if (t < off) red[t] += red[t + off];
        __syncthreads();
    }
    if (t == 0) pre[b * 128 + o] = red[0] + bias[o];
}

__device__ __forceinline__ float bsum128(float v, float* red) {
    int t = threadIdx.x;
    red[t] = v;
    __syncthreads();
#pragma unroll
    for (int off = 64; off; off >>= 1) {
        if (t < off) red[t] += red[t + off];
        __syncthreads();
    }
    float s = red[0];
    __syncthreads();
    return s;
}

// LN1 + relu + fc2 + LN2 + relu + fc3 + sigmoid, one block per batch row (128 threads)
__global__ void head_kernel(const float* __restrict__ pre, const float* __restrict__ g1,
                            const float* __restrict__ bb1, const float* __restrict__ w2,
                            const float* __restrict__ b2v, const float* __restrict__ g2,
                            const float* __restrict__ bb2, const float* __restrict__ w3,
                            const float* __restrict__ b3, float* __restrict__ out) {
    __shared__ float red[128];
    __shared__ float ybuf[128];
    int b = blockIdx.x, t = threadIdx.x;
    float x = pre[b * 128 + t];
    float mu = bsum128(x, red) * (1.f / 128.f);
    float d = x - mu;
    float var = bsum128(d * d, red) * (1.f / 128.f);
    float y = fmaxf(d * rsqrtf(var + LN_EPS) * g1[t] + bb1[t], 0.f);
    ybuf[t] = y;
    __syncthreads();
    float p = 0.f;
    if (t < 64) {
        const float* wr = w2 + t * 128;
#pragma unroll 8
        for (int i = 0; i < 128; i++) p += ybuf[i] * wr[i];
        p += b2v[t];
    }
    float mu2 = bsum128((t < 64) ? p : 0.f, red) * (1.f / 64.f);
    float dd = p - mu2;
    float var2 = bsum128((t < 64) ? dd * dd : 0.f, red) * (1.f / 64.f);
    float z = (t < 64) ? fmaxf(dd * rsqrtf(var2 + LN_EPS) * g2[t] + bb2[t], 0.f) : 0.f;
    float s = bsum128((t < 64) ? z * w3[t] : 0.f, red);
    if (t == 0) out[b] = 1.f / (1.f + expf(-(s + b3[0])));
}

// ---------------- launch ----------------
extern "C" void kernel_launch(void* const* d_in, const int* in_sizes, int n_in,
                              void* d_out, int out_size) {
    const float* x1 = (const float*)d_in[0];
    const int* ei1 = (const int*)d_in[1];
    const float* x2 = (const float*)d_in[3];
    const int* ei2 = (const int*)d_in[4];
    const float* w1l = (const float*)d_in[5];
    const float* b1l = (const float*)d_in[6];
    const float* w1r = (const float*)d_in[7];
    const float* w2l = (const float*)d_in[8];
    const float* b2l = (const float*)d_in[9];
    const float* w2r = (const float*)d_in[10];
    const float* fc1w = (const float*)d_in[11];
    const float* fc1b = (const float*)d_in[12];
    const float* ln1g = (const float*)d_in[13];
    const float* ln1b = (const float*)d_in[14];
    const float* fc2w = (const float*)d_in[15];
    const float* fc2b = (const float*)d_in[16];
    const float* ln2g = (const float*)d_in[17];
    const float* ln2b = (const float*)d_in[18];
    const float* fc3w = (const float*)d_in[19];
    const float* fc3b = (const float*)d_in[20];
    float* out = (float*)d_out;

    int N1 = in_sizes[0] / FIN;
    int E1 = in_sizes[1] / 2;
    int N2 = in_sizes[3] / FIN;
    int E2 = in_sizes[4] / 2;

    void* p;
    float *z1, *mean1, *h1, *o1, *z2, *mean2, *h2, *o2, *feat, *pre1;
    int *cnt1, *offs1, *cur1, *csr1, *cnt2, *offs2, *cur2, *csr2, *sel;
    unsigned long long* codes;
    cudaGetSymbolAddress(&p, d_z1);    z1 = (float*)p;
    cudaGetSymbolAddress(&p, d_mean1); mean1 = (float*)p;
    cudaGetSymbolAddress(&p, d_h1);    h1 = (float*)p;
    cudaGetSymbolAddress(&p, d_o1);    o1 = (float*)p;
    cudaGetSymbolAddress(&p, d_cnt1);  cnt1 = (int*)p;
    cudaGetSymbolAddress(&p, d_offs1); offs1 = (int*)p;
    cudaGetSymbolAddress(&p, d_cur1);  cur1 = (int*)p;
    cudaGetSymbolAddress(&p, d_csr1);  csr1 = (int*)p;
    cudaGetSymbolAddress(&p, d_z2);    z2 = (float*)p;
    cudaGetSymbolAddress(&p, d_mean2); mean2 = (float*)p;
    cudaGetSymbolAddress(&p, d_h2);    h2 = (float*)p;
    cudaGetSymbolAddress(&p, d_o2);    o2 = (float*)p;
    cudaGetSymbolAddress(&p, d_cnt2);  cnt2 = (int*)p;
    cudaGetSymbolAddress(&p, d_offs2); offs2 = (int*)p;
    cudaGetSymbolAddress(&p, d_cur2);  cur2 = (int*)p;
    cudaGetSymbolAddress(&p, d_csr2);  csr2 = (int*)p;
    cudaGetSymbolAddress(&p, d_codes); codes = (unsigned long long*)p;
    cudaGetSymbolAddress(&p, d_sel);   sel = (int*)p;
    cudaGetSymbolAddress(&p, d_feat);  feat = (float*)p;
    cudaGetSymbolAddress(&p, d_pre1);  pre1 = (float*)p;

    // ---- CSR build (both graphs) ----
    zero_int_kernel<<<cdiv(N1, 256), 256>>>(cnt1, N1);
    zero_int_kernel<<<1, 256>>>(cnt2, N2);
    count_kernel<<<cdiv(E1, 256), 256>>>(ei1, E1, cnt1);
    count_kernel<<<cdiv(E2, 256), 256>>>(ei2, E2, cnt2);
    scan_kernel<<<1, 1024>>>(cnt1, offs1, cur1, N1);
    scan_kernel<<<1, 1024>>>(cnt2, offs2, cur2, N2);
    fill_kernel<<<cdiv(E1, 256), 256>>>(ei1, E1, cur1, csr1);
    fill_kernel<<<cdiv(E2, 256), 256>>>(ei2, E2, cur2, csr2);

    // ---- graph1 GNN ----
    gemm_k128<128, false><<<cdiv(N1, 128), 256>>>(x1, w1l, nullptr, nullptr, z1, N1);
    agg_kernel<128><<<N1, 128>>>(z1, offs1, csr1, mean1);
    gemm_k128<128, true><<<cdiv(N1, 128), 256>>>(x1, w1r, b1l, mean1, h1, N1);
    gemm_k128<64, false><<<cdiv(N1, 128), 256>>>(h1, w2l, nullptr, nullptr, z1, N1);
    agg_kernel<64><<<N1, 64>>>(z1, offs1, csr1, mean1);
    gemm_k128<64, true><<<cdiv(N1, 128), 256>>>(h1, w2r, b2l, mean1, o1, N1);

    // ---- graph2 GNN (tiny) ----
    gemm_k128<128, false><<<cdiv(N2, 128), 256>>>(x2, w1l, nullptr, nullptr, z2, N2);
    agg_kernel<128><<<N2, 128>>>(z2, offs2, csr2, mean2);
    gemm_k128<128, true><<<cdiv(N2, 128), 256>>>(x2, w1r, b1l, mean2, h2, N2);
    gemm_k128<64, false><<<cdiv(N2, 128), 256>>>(h2, w2l, nullptr, nullptr, z2, N2);
    agg_kernel<64><<<N2, 64>>>(z2, offs2, csr2, mean2);
    gemm_k128<64, true><<<cdiv(N2, 128), 256>>>(h2, w2r, b2l, mean2, o2, N2);

    // ---- key + top-k + sparse dist + MLP head ----
    key_kernel<<<cdiv(N1, 256), 256>>>(o1, o2 + (long)(N2 - 1) * 64, codes, N1);
    topk_kernel<<<BATCH, 512>>>(codes, sel);
    dist_kernel<<<BATCH * TOPK, 256>>>(o1, o2, sel, feat, N2);
    fc1_kernel<<<dim3(128, BATCH), 256>>>(feat, fc1w, fc1b, pre1, TOPK * N2);
    head_kernel<<<BATCH, 128>>>(pre1, ln1g, ln1b, fc2w, fc2b, ln2g, ln2b, fc3w, fc3b, out);
}

// round 6
// speedup vs baseline: 1.5860x; 1.5800x over previous
#include <cuda_runtime.h>
#include <math.h>

#define N1C 50000
#define E1C 1000000
#define N2C 199
#define E2C 4000
#define MC (N1C + N2C)
#define FIN 128
#define BATCH 10
#define NPGC 5000
#define TOPK 50
#define LN_EPS 1e-5f

static inline int cdiv(int a, int b) { return (a + b - 1) / b; }

// ---------------- scratch ----------------
__device__ float d_z[MC * 128];   // aggregation-path transform
__device__ float d_r[MC * 128];   // root-path transform
__device__ float d_h[MC * 128];   // layer1 output
__device__ float d_o[MC * 64];    // layer2 output (out1 | out2)
__device__ int d_cnt[MC];
__device__ int d_offs[MC + 1];
__device__ int d_cur[MC];
__device__ int d_csr[E1C + E2C];
__device__ unsigned long long d_codes[N1C];
__device__ int d_sel[BATCH * TOPK];
__device__ float d_feat[BATCH * TOPK * N2C];
__device__ float d_pre1[BATCH * 128];

// ---------------- f32x2 helpers ----------------
__device__ __forceinline__ unsigned long long dup2(float x) {
    unsigned long long r;
    asm("mov.b64 %0, {%1, %1};" : "=l"(r) : "r"(__float_as_uint(x)));
    return r;
}
__device__ __forceinline__ void ffma2(unsigned long long& d, unsigned long long a,
                                      unsigned long long b) {
    asm("fma.rn.f32x2 %0, %1, %2, %0;" : "+l"(d) : "l"(a), "l"(b));
}

// ---------------- CSR build ----------------
__global__ void zero_int_kernel(int* p, int n) {
    int i = blockIdx.x * blockDim.x + threadIdx.x;
    if (i < n) p[i] = 0;
}

__global__ void count_kernel(const int* __restrict__ ei, int E, int off, int* __restrict__ cnt) {
    int e = blockIdx.x * blockDim.x + threadIdx.x;
    if (e < E) atomicAdd(&cnt[off + ei[E + e]], 1);
}

__global__ void scan_kernel(const int* __restrict__ cnt, int* __restrict__ offs,
                            int* __restrict__ cur, int n) {
    __shared__ int wsums[32];
    __shared__ int carry_s;
    int t = threadIdx.x;
    int lane = t & 31, wid = t >> 5;
    if (t == 0) carry_s = 0;
    __syncthreads();
    for (int base = 0; base < n; base += 1024) {
        int i = base + t;
        int v = (i < n) ? cnt[i] : 0;
        int x = v;
#pragma unroll
        for (int d = 1; d < 32; d <<= 1) {
            int y = __shfl_up_sync(0xffffffffu, x, d);
            if (lane >= d) x += y;
        }
        if (lane == 31) wsums[wid] = x;
        __syncthreads();
        if (wid == 0) {
            int s = wsums[lane];
#pragma unroll
            for (int d = 1; d < 32; d <<= 1) {
                int y = __shfl_up_sync(0xffffffffu, s, d);
                if (lane >= d) s += y;
            }
            wsums[lane] = s;
        }
        __syncthreads();
        int c = carry_s;
        int wbase = wid ? wsums[wid - 1] : 0;
        int excl = c + wbase + x - v;
        if (i < n) { offs[i] = excl; cur[i] = excl; }
        int total = wsums[31];
        __syncthreads();
        if (t == 0) carry_s = c + total;
        __syncthreads();
    }
    if (threadIdx.x == 0) offs[n] = carry_s;
}

__global__ void fill_kernel(const int* __restrict__ ei, int E, int off,
                            int* __restrict__ cur, int* __restrict__ csr) {
    int e = blockIdx.x * blockDim.x + threadIdx.x;
    if (e < E) {
        int dst = off + ei[E + e];
        int pos = atomicAdd(&cur[dst], 1);
        csr[pos] = off + ei[e];
    }
}

// ---------------- f32x2 GEMM, K=128: O[M, BN] = A[M,128] @ W[BN,128]^T ----------------
// blockIdx.y selects (Wa->Oa) or (Wb->Ob). A rows [0,M1) from A1, [M1,Mtot) from A2.
template <int TN>
__global__ void __launch_bounds__(256)
gemm_kernel(const float* __restrict__ A1, int M1, const float* __restrict__ A2, int Mtot,
            const float* __restrict__ Wa, const float* __restrict__ Wb,
            float* __restrict__ Oa, float* __restrict__ Ob) {
    constexpr int BN = TN * 16;
    __shared__ float As[128][20];
    __shared__ float Ws[16][BN + 2];
    int t = threadIdx.x;
    int tx = t & 15, ty = t >> 4;
    int row0 = blockIdx.x * 128;
    const float* W = blockIdx.y ? Wb : Wa;
    float* O = blockIdx.y ? Ob : Oa;
    unsigned long long acc[8][TN / 2];
#pragma unroll
    for (int i = 0; i < 8; i++)
#pragma unroll
        for (int j = 0; j < TN / 2; j++) acc[i][j] = 0ull;

    for (int k0 = 0; k0 < 128; k0 += 16) {
        // A tile: 128 x 16 floats = 512 float4, 2 per thread
#pragma unroll
        for (int i = 0; i < 2; i++) {
            int idx = t + i * 256;
            int rr = idx >> 2;
            int kq = (idx & 3) * 4;
            int gr = row0 + rr;
            float4 v = make_float4(0.f, 0.f, 0.f, 0.f);
            if (gr < M1) v = *(const float4*)(A1 + (size_t)gr * 128 + k0 + kq);
            else if (gr < Mtot) v = *(const float4*)(A2 + (size_t)(gr - M1) * 128 + k0 + kq);
            *(float4*)&As[rr][kq] = v;
        }
        // W tile: BN x 16 floats, transposed store
#pragma unroll
        for (int i = 0; i < BN / 64; i++) {
            int idx = t + i * 256;
            int n = idx >> 2;
            int kq = (idx & 3) * 4;
            float4 v = *(const float4*)(W + (size_t)n * 128 + k0 + kq);
            Ws[kq + 0][n] = v.x;
            Ws[kq + 1][n] = v.y;
            Ws[kq + 2][n] = v.z;
            Ws[kq + 3][n] = v.w;
        }
        __syncthreads();
#pragma unroll 4
        for (int k = 0; k < 16; k++) {
            unsigned long long ad[8];
#pragma unroll
            for (int i = 0; i < 8; i++) ad[i] = dup2(As[ty * 8 + i][k]);
            unsigned long long b2[TN / 2];
#pragma unroll
            for (int j = 0; j < TN / 2; j++)
                b2[j] = *(const unsigned long long*)&Ws[k][tx * TN + 2 * j];
#pragma unroll
            for (int i = 0; i < 8; i++)
#pragma unroll
                for (int j = 0; j < TN / 2; j++) ffma2(acc[i][j], ad[i], b2[j]);
        }
        __syncthreads();
    }
    int c0 = tx * TN;
#pragma unroll
    for (int i = 0; i < 8; i++) {
        int rr = row0 + ty * 8 + i;
        if (rr < Mtot) {
            float* op = O + (size_t)rr * BN + c0;
#pragma unroll
            for (int q = 0; q < TN / 4; q++) {
                ulonglong2 s;
                s.x = acc[i][2 * q];
                s.y = acc[i][2 * q + 1];
                *(ulonglong2*)(op + 4 * q) = s;
            }
        }
    }
}

// ---------------- fused mean aggregation + residual + bias + relu ----------------
// out[g] = relu( mean_{src in N(g)} z[src] + r[g] + bias )
template <int F>
__global__ void agg_fuse_kernel(const float* __restrict__ z, const float* __restrict__ rres,
                                const float* __restrict__ bias, const int* __restrict__ offs,
                                const int* __restrict__ csr, float* __restrict__ out, int M) {
    constexpr int LPN = F / 4;
    int tid = blockIdx.x * blockDim.x + threadIdx.x;
    int g = tid / LPN;
    int lane = tid % LPN;
    if (g >= M) return;
    int s = offs[g], e = offs[g + 1];
    float4 a0 = make_float4(0.f, 0.f, 0.f, 0.f);
    float4 a1 = make_float4(0.f, 0.f, 0.f, 0.f);
    int i = s;
    for (; i + 2 <= e; i += 2) {
        int s0 = csr[i], s1 = csr[i + 1];
        float4 v0 = *(const float4*)(z + (size_t)s0 * F + lane * 4);
        float4 v1 = *(const float4*)(z + (size_t)s1 * F + lane * 4);
        a0.x += v0.x; a0.y += v0.y; a0.z += v0.z; a0.w += v0.w;
        a1.x += v1.x; a1.y += v1.y; a1.z += v1.z; a1.w += v1.w;
    }
    if (i < e) {
        int s0 = csr[i];
        float4 v0 = *(const float4*)(z + (size_t)s0 * F + lane * 4);
        a0.x += v0.x; a0.y += v0.y; a0.z += v0.z; a0.w += v0.w;
    }
    float inv = 1.f / fmaxf((float)(e - s), 1.f);
    float4 rv = *(const float4*)(rres + (size_t)g * F + lane * 4);
    float4 bv = *(const float4*)(bias + lane * 4);
    float4 o;
    o.x = fmaxf((a0.x + a1.x) * inv + rv.x + bv.x, 0.f);
    o.y = fmaxf((a0.y + a1.y) * inv + rv.y + bv.y, 0.f);
    o.z = fmaxf((a0.z + a1.z) * inv + rv.z + bv.z, 0.f);
    o.w = fmaxf((a0.w + a1.w) * inv + rv.w + bv.w, 0.f);
    *(float4*)(out + (size_t)g * F + lane * 4) = o;
}

// ---------------- sort key per node ----------------
__global__ void key_kernel(const float* __restrict__ o1, const float* __restrict__ o2last,
                           unsigned long long* __restrict__ codes, int n) {
    int i = blockIdx.x * blockDim.x + threadIdx.x;
    if (i >= n) return;
    const float* r = o1 + (size_t)i * 64;
    float a2 = 0.f, dot = 0.f, b2 = 0.f;
#pragma unroll 8
    for (int d = 0; d < 64; d++) {
        float v = r[d], w = o2last[d];
        a2 += v * v;
        dot += v * w;
        b2 += w * w;
    }
    float key = a2 + b2 - 2.f * dot;
    unsigned u = __float_as_uint(key);
    u = (u & 0x80000000u) ? ~u : (u | 0x80000000u);
    codes[i] = ((unsigned long long)(~u) << 32) | (unsigned)i;
}

__device__ __forceinline__ unsigned long long umin64(unsigned long long a, unsigned long long b) {
    return a < b ? a : b;
}

// one block per graph: select 50 smallest codes, in order
__global__ void topk_kernel(const unsigned long long* __restrict__ codes,
                            int* __restrict__ sel, int npg) {
    __shared__ unsigned long long s[NPGC];
    __shared__ unsigned long long wmin[16];
    int b = blockIdx.x, t = threadIdx.x;
    int lane = t & 31, wid = t >> 5;
    for (int i = t; i < npg; i += 512) s[i] = codes[b * npg + i];
    __syncthreads();
    for (int k = 0; k < TOPK; k++) {
        unsigned long long m = ~0ull;
        for (int i = t; i < npg; i += 512) m = umin64(m, s[i]);
#pragma unroll
        for (int d = 16; d; d >>= 1) m = umin64(m, __shfl_xor_sync(0xffffffffu, m, d));
        if (lane == 0) wmin[wid] = m;
        __syncthreads();
        if (t == 0) {
            unsigned long long bb = wmin[0];
#pragma unroll
            for (int j = 1; j < 16; j++) bb = umin64(bb, wmin[j]);
            int gi = (int)(bb & 0xffffffffu);
            sel[b * TOPK + k] = gi;
            s[gi - b * npg] = ~0ull;
        }
        __syncthreads();
    }
}

// dist rows for selected nodes only
__global__ void dist_kernel(const float* __restrict__ o1, const float* __restrict__ o2,
                            const int* __restrict__ sel, float* __restrict__ feat, int n2) {
    __shared__ float o1s[64];
    int bk = blockIdx.x;
    int t = threadIdx.x;
    int g = sel[bk];
    if (t < 64) o1s[t] = o1[(size_t)g * 64 + t];
    __syncthreads();
    if (t < n2) {
        float a2 = 0.f, b2 = 0.f, dot = 0.f;
        const float* q = o2 + (size_t)t * 64;
#pragma unroll 8
        for (int d = 0; d < 64; d++) {
            float v = o1s[d], w = q[d];
            a2 += v * v;
            b2 += w * w;
            dot += v * w;
        }
        float d2 = a2 + b2 - 2.f * dot;
        feat[bk * n2 + t] = sqrtf(fmaxf(d2, 0.f));
    }
}

__global__ void fc1_kernel(const float* __restrict__ feat, const float* __restrict__ w,
                           const float* __restrict__ bias, float* __restrict__ pre, int L) {
    __shared__ float red[256];
    int o = blockIdx.x, b = blockIdx.y, t = threadIdx.x;
    const float* f = feat + (size_t)b * L;
    const float* wr = w + (size_t)o * L;
    float acc = 0.f;
    for (int i = t; i < L; i += 256) acc += f[i] * wr[i];
    red[t] = acc;
    __syncthreads();
    for (int off = 128; off; off >>= 1) {
        if (t < off) red[t] += red[t + off];
        __syncthreads();
    }
    if (t == 0) pre[b * 128 + o] = red[0] + bias[o];
}

__device__ __forceinline__ float bsum128(float v, float* red) {
    int t = threadIdx.x;
    red[t] = v;
    __syncthreads();
#pragma unroll
    for (int off = 64; off; off >>= 1) {
        if (t < off) red[t] += red[t + off];
        __syncthreads();
    }
    float s = red[0];
    __syncthreads();
    return s;
}

__global__ void head_kernel(const float* __restrict__ pre, const float* __restrict__ g1,
                            const float* __restrict__ bb1, const float* __restrict__ w2,
                            const float* __restrict__ b2v, const float* __restrict__ g2,
                            const float* __restrict__ bb2, const float* __restrict__ w3,
                            const float* __restrict__ b3, float* __restrict__ out) {
    __shared__ float red[128];
    __shared__ float ybuf[128];
    int b = blockIdx.x, t = threadIdx.x;
    float x = pre[b * 128 + t];
    float mu = bsum128(x, red) * (1.f / 128.f);
    float d = x - mu;
    float var = bsum128(d * d, red) * (1.f / 128.f);
    float y = fmaxf(d * rsqrtf(var + LN_EPS) * g1[t] + bb1[t], 0.f);
    ybuf[t] = y;
    __syncthreads();
    float p = 0.f;
    if (t < 64) {
        const float* wr = w2 + t * 128;
#pragma unroll 8
        for (int i = 0; i < 128; i++) p += ybuf[i] * wr[i];
        p += b2v[t];
    }
    float mu2 = bsum128((t < 64) ? p : 0.f, red) * (1.f / 64.f);
    float dd = p - mu2;
    float var2 = bsum128((t < 64) ? dd * dd : 0.f, red) * (1.f / 64.f);
    float z = (t < 64) ? fmaxf(dd * rsqrtf(var2 + LN_EPS) * g2[t] + bb2[t], 0.f) : 0.f;
    float s = bsum128((t < 64) ? z * w3[t] : 0.f, red);
    if (t == 0) out[b] = 1.f / (1.f + expf(-(s + b3[0])));
}

// ---------------- launch ----------------
extern "C" void kernel_launch(void* const* d_in, const int* in_sizes, int n_in,
                              void* d_out, int out_size) {
    const float* x1 = (const float*)d_in[0];
    const int* ei1 = (const int*)d_in[1];
    const float* x2 = (const float*)d_in[3];
    const int* ei2 = (const int*)d_in[4];
    const float* w1l = (const float*)d_in[5];
    const float* b1l = (const float*)d_in[6];
    const float* w1r = (const float*)d_in[7];
    const float* w2l = (const float*)d_in[8];
    const float* b2l = (const float*)d_in[9];
    const float* w2r = (const float*)d_in[10];
    const float* fc1w = (const float*)d_in[11];
    const float* fc1b = (const float*)d_in[12];
    const float* ln1g = (const float*)d_in[13];
    const float* ln1b = (const float*)d_in[14];
    const float* fc2w = (const float*)d_in[15];
    const float* fc2b = (const float*)d_in[16];
    const float* ln2g = (const float*)d_in[17];
    const float* ln2b = (const float*)d_in[18];
    const float* fc3w = (const float*)d_in[19];
    const float* fc3b = (const float*)d_in[20];
    float* out = (float*)d_out;

    int N1 = in_sizes[0] / FIN;
    int E1 = in_sizes[1] / 2;
    int N2 = in_sizes[3] / FIN;
    int E2 = in_sizes[4] / 2;
    int Mtot = N1 + N2;
    int npg = N1 / BATCH;

    void* p;
    float *z, *r, *h, *o, *feat, *pre1;
    int *cnt, *offs, *cur, *csr, *sel;
    unsigned long long* codes;
    cudaGetSymbolAddress(&p, d_z);     z = (float*)p;
    cudaGetSymbolAddress(&p, d_r);     r = (float*)p;
    cudaGetSymbolAddress(&p, d_h);     h = (float*)p;
    cudaGetSymbolAddress(&p, d_o);     o = (float*)p;
    cudaGetSymbolAddress(&p, d_cnt);   cnt = (int*)p;
    cudaGetSymbolAddress(&p, d_offs);  offs = (int*)p;
    cudaGetSymbolAddress(&p, d_cur);   cur = (int*)p;
    cudaGetSymbolAddress(&p, d_csr);   csr = (int*)p;
    cudaGetSymbolAddress(&p, d_codes); codes = (unsigned long long*)p;
    cudaGetSymbolAddress(&p, d_sel);   sel = (int*)p;
    cudaGetSymbolAddress(&p, d_feat);  feat = (float*)p;
    cudaGetSymbolAddress(&p, d_pre1);  pre1 = (float*)p;

    // ---- combined CSR build ----
    zero_int_kernel<<<cdiv(Mtot, 256), 256>>>(cnt, Mtot);
    count_kernel<<<cdiv(E1, 256), 256>>>(ei1, E1, 0, cnt);
    count_kernel<<<cdiv(E2, 256), 256>>>(ei2, E2, N1, cnt);
    scan_kernel<<<1, 1024>>>(cnt, offs, cur, Mtot);
    fill_kernel<<<cdiv(E1, 256), 256>>>(ei1, E1, 0, cur, csr);
    fill_kernel<<<cdiv(E2, 256), 256>>>(ei2, E2, N1, cur, csr);

    // ---- layer 1: z = X@w1l^T, r = X@w1r^T; h = relu(mean(z) + r + b1l) ----
    gemm_kernel<8><<<dim3(cdiv(Mtot, 128), 2), 256>>>(x1, N1, x2, Mtot, w1l, w1r, z, r);
    agg_fuse_kernel<128><<<cdiv(Mtot * 32, 256), 256>>>(z, r, b1l, offs, csr, h, Mtot);

    // ---- layer 2: z = h@w2l^T, r = h@w2r^T; o = relu(mean(z) + r + b2l) ----
    gemm_kernel<4><<<dim3(cdiv(Mtot, 128), 2), 256>>>(h, Mtot, nullptr, Mtot, w2l, w2r, z, r);
    agg_fuse_kernel<64><<<cdiv(Mtot * 16, 256), 256>>>(z, r, b2l, offs, csr, o, Mtot);

    // ---- key + top-k + sparse dist + MLP head ----
    key_kernel<<<cdiv(N1, 256), 256>>>(o, o + (size_t)(Mtot - 1) * 64, codes, N1);
    topk_kernel<<<BATCH, 512>>>(codes, sel, npg);
    dist_kernel<<<BATCH * TOPK, 256>>>(o, o + (size_t)N1 * 64, sel, feat, N2);
    fc1_kernel<<<dim3(128, BATCH), 256>>>(feat, fc1w, fc1b, pre1, TOPK * N2);
    head_kernel<<<BATCH, 128>>>(pre1, ln1g, ln1b, fc2w, fc2b, ln2g, ln2b, fc3w, fc3b, out);
}